// round 1
// baseline (speedup 1.0000x reference)
#include <cuda_runtime.h>
#include <math.h>

#define BATCH 2
#define CHN 256
#define NHEAD 8
#define HDIM 32
#define HWTOK 4096
#define NGROUP 32
#define CPG 8
#define GN_EPS 1e-5f

// scratch (static device arrays; allocation-free per harness rules)
__device__ float g_h[BATCH * CHN * HWTOK];        // groupnorm output   [b][c][t]
__device__ float g_qkv[BATCH * 3 * CHN * HWTOK];  // qkv                [b][o][t]
__device__ float g_ao[BATCH * CHN * HWTOK];       // attention output   [b][c][t]

// ---------------------------------------------------------------------------
// GroupNorm: one block per (b, group); group = 8 channels x 4096 = 32768 elems
// ---------------------------------------------------------------------------
__global__ __launch_bounds__(256) void gn_kernel(const float* __restrict__ x,
                                                 const float* __restrict__ gamma,
                                                 const float* __restrict__ beta) {
    int b = blockIdx.x / NGROUP;
    int g = blockIdx.x % NGROUP;
    const float* xg = x + ((size_t)b * CHN + g * CPG) * HWTOK;
    float* hg = g_h + ((size_t)b * CHN + g * CPG) * HWTOK;
    const int N = CPG * HWTOK;

    float s = 0.f, ss = 0.f;
    for (int i = threadIdx.x; i < N; i += 256) {
        float v = xg[i];
        s += v;
        ss += v * v;
    }
#pragma unroll
    for (int o = 16; o; o >>= 1) {
        s += __shfl_xor_sync(0xffffffffu, s, o);
        ss += __shfl_xor_sync(0xffffffffu, ss, o);
    }
    __shared__ float red0[8], red1[8];
    int wid = threadIdx.x >> 5, lid = threadIdx.x & 31;
    if (lid == 0) { red0[wid] = s; red1[wid] = ss; }
    __syncthreads();
    __shared__ float s_mean, s_rstd;
    if (threadIdx.x == 0) {
        float S = 0.f, SS = 0.f;
        for (int w = 0; w < 8; w++) { S += red0[w]; SS += red1[w]; }
        float mean = S / (float)N;
        float var = SS / (float)N - mean * mean;
        s_mean = mean;
        s_rstd = rsqrtf(var + GN_EPS);
    }
    __syncthreads();
    float mean = s_mean, rstd = s_rstd;
    for (int i = threadIdx.x; i < N; i += 256) {
        int c = g * CPG + i / HWTOK;
        hg[i] = (xg[i] - mean) * rstd * gamma[c] + beta[c];
    }
}

// ---------------------------------------------------------------------------
// 1x1-conv GEMM: out[b][o][t] = sum_c W[o][c] * Hin[b][c][t] + bias[o] (+resid)
// MODE 0: Hin=g_h,  out=g_qkv (OC=768).  MODE 1: Hin=g_ao, out=ext, resid=x.
// Block: 256 threads (16x16), 64x64 output tile, K-tiles of 16.
// ---------------------------------------------------------------------------
template <int MODE>
__global__ __launch_bounds__(256) void mm_kernel(const float* __restrict__ W,
                                                 const float* __restrict__ bias,
                                                 const float* __restrict__ resid,
                                                 float* __restrict__ outx) {
    const int OC = (MODE == 0) ? 3 * CHN : CHN;
    const float* Hin = (MODE == 0) ? g_h : g_ao;
    float* out = (MODE == 0) ? g_qkv : outx;

    int b = blockIdx.z;
    int tb = blockIdx.x * 64;
    int ob = blockIdx.y * 64;
    int tx = threadIdx.x & 15, ty = threadIdx.x >> 4;

    __shared__ float sW[16][65];  // [k][o]
    __shared__ float sH[16][64];  // [k][t]
    float acc[4][4] = {};
    const float* Hb = Hin + (size_t)b * CHN * HWTOK;

    for (int kb = 0; kb < CHN; kb += 16) {
#pragma unroll
        for (int it = 0; it < 4; it++) {
            int idx = threadIdx.x + it * 256;
            int o = idx >> 4, k = idx & 15;
            sW[k][o] = W[(size_t)(ob + o) * CHN + kb + k];
        }
#pragma unroll
        for (int it = 0; it < 4; it++) {
            int idx = threadIdx.x + it * 256;
            int k = idx >> 6, t = idx & 63;
            sH[k][t] = Hb[(size_t)(kb + k) * HWTOK + tb + t];
        }
        __syncthreads();
#pragma unroll
        for (int kk = 0; kk < 16; kk++) {
            float a[4], bb[4];
#pragma unroll
            for (int i = 0; i < 4; i++) a[i] = sW[kk][ty + 16 * i];
#pragma unroll
            for (int j = 0; j < 4; j++) bb[j] = sH[kk][tx + 16 * j];
#pragma unroll
            for (int i = 0; i < 4; i++)
#pragma unroll
                for (int j = 0; j < 4; j++) acc[i][j] += a[i] * bb[j];
        }
        __syncthreads();
    }
#pragma unroll
    for (int i = 0; i < 4; i++) {
        int o = ob + ty + 16 * i;
        float bi = bias[o];
#pragma unroll
        for (int j = 0; j < 4; j++) {
            int t = tb + tx + 16 * j;
            float v = acc[i][j] + bi;
            if (MODE == 1) v += resid[((size_t)b * CHN + o) * HWTOK + t];
            out[((size_t)b * OC + o) * HWTOK + t] = v;
        }
    }
}

// ---------------------------------------------------------------------------
// Flash attention, fp32 SIMT. One block per (b*NH, q-tile of 64).
// 128 threads: tx = tid&7 (0..7), ty = tid>>3 (0..15).
// S tile: rows ty+16i (i<4), cols tx+8j (j<8).  O tile: rows ty+16i, d tx+8j (j<4).
// ---------------------------------------------------------------------------
__global__ __launch_bounds__(128) void attn_kernel() {
    int bh = blockIdx.x;            // 0..15
    int b = bh >> 3, n = bh & 7;
    int qb = blockIdx.y * 64;
    int tid = threadIdx.x;
    int tx = tid & 7, ty = tid >> 3;

    __shared__ float sQ[64][33];
    __shared__ float sK[64][33];
    __shared__ float sV[64][33];
    __shared__ float sS[64][65];
    __shared__ float sm_m[64], sm_l[64], sm_c[64];

    const float scale = 0.17677669529663687f;  // 1/sqrt(32)
    const float* Qp = g_qkv + ((size_t)b * 768 + n * HDIM) * HWTOK;
    const float* Kp = g_qkv + ((size_t)b * 768 + 256 + n * HDIM) * HWTOK;
    const float* Vp = g_qkv + ((size_t)b * 768 + 512 + n * HDIM) * HWTOK;

    // load Q tile (pre-scaled)
#pragma unroll
    for (int it = 0; it < 16; it++) {
        int idx = tid + it * 128;
        int d = idx >> 6, r = idx & 63;
        sQ[r][d] = Qp[(size_t)d * HWTOK + qb + r] * scale;
    }
    if (tid < 64) { sm_m[tid] = -3.0e38f; sm_l[tid] = 0.f; }

    float O[4][4] = {};

    for (int kc = 0; kc < HWTOK; kc += 64) {
        __syncthreads();  // O-update done / Q+init visible
#pragma unroll
        for (int it = 0; it < 16; it++) {
            int idx = tid + it * 128;
            int d = idx >> 6, c = idx & 63;
            sK[c][d] = Kp[(size_t)d * HWTOK + kc + c];
            sV[c][d] = Vp[(size_t)d * HWTOK + kc + c];
        }
        __syncthreads();

        // S = (Q*scale) K^T
        float S[4][8] = {};
#pragma unroll
        for (int d = 0; d < 32; d++) {
            float qv[4], kv[8];
#pragma unroll
            for (int i = 0; i < 4; i++) qv[i] = sQ[ty + 16 * i][d];
#pragma unroll
            for (int j = 0; j < 8; j++) kv[j] = sK[tx + 8 * j][d];
#pragma unroll
            for (int i = 0; i < 4; i++)
#pragma unroll
                for (int j = 0; j < 8; j++) S[i][j] += qv[i] * kv[j];
        }
#pragma unroll
        for (int i = 0; i < 4; i++)
#pragma unroll
            for (int j = 0; j < 8; j++) sS[ty + 16 * i][tx + 8 * j] = S[i][j];
        __syncthreads();

        // online softmax: 2 threads per row
        {
            int row = tid >> 1, sub = tid & 1;
            float m = -3.0e38f;
#pragma unroll
            for (int c = 0; c < 32; c++) m = fmaxf(m, sS[row][sub * 32 + c]);
            m = fmaxf(m, __shfl_xor_sync(0xffffffffu, m, 1));
            float mprev = sm_m[row];
            float mnew = fmaxf(mprev, m);
            float lsum = 0.f;
#pragma unroll
            for (int c = 0; c < 32; c++) {
                float p = __expf(sS[row][sub * 32 + c] - mnew);
                sS[row][sub * 32 + c] = p;
                lsum += p;
            }
            lsum += __shfl_xor_sync(0xffffffffu, lsum, 1);
            if (sub == 0) {
                float corr = __expf(mprev - mnew);
                sm_c[row] = corr;
                sm_m[row] = mnew;
                sm_l[row] = sm_l[row] * corr + lsum;
            }
        }
        __syncthreads();

        // O = O*corr + P V
        float cr[4];
#pragma unroll
        for (int i = 0; i < 4; i++) cr[i] = sm_c[ty + 16 * i];
#pragma unroll
        for (int i = 0; i < 4; i++)
#pragma unroll
            for (int j = 0; j < 4; j++) O[i][j] *= cr[i];
#pragma unroll
        for (int k = 0; k < 64; k++) {
            float vv[4];
#pragma unroll
            for (int j = 0; j < 4; j++) vv[j] = sV[k][tx + 8 * j];
#pragma unroll
            for (int i = 0; i < 4; i++) {
                float p = sS[ty + 16 * i][k];
#pragma unroll
                for (int j = 0; j < 4; j++) O[i][j] += p * vv[j];
            }
        }
    }
    __syncthreads();

    // normalize and stage through smem (reuse sQ) for coalesced global store
#pragma unroll
    for (int i = 0; i < 4; i++) {
        int r = ty + 16 * i;
        float inv = 1.f / sm_l[r];
#pragma unroll
        for (int j = 0; j < 4; j++) sQ[r][tx + 8 * j] = O[i][j] * inv;
    }
    __syncthreads();
    float* aop = g_ao + ((size_t)b * CHN + n * HDIM) * HWTOK;
#pragma unroll
    for (int it = 0; it < 16; it++) {
        int idx = tid + it * 128;
        int d = idx >> 6, r = idx & 63;
        aop[(size_t)d * HWTOK + qb + r] = sQ[r][d];
    }
}

// ---------------------------------------------------------------------------
extern "C" void kernel_launch(void* const* d_in, const int* in_sizes, int n_in,
                              void* d_out, int out_size) {
    const float* x = (const float*)d_in[0];
    const float* w_qkv = (const float*)d_in[1];
    const float* b_qkv = (const float*)d_in[2];
    const float* w_proj = (const float*)d_in[3];
    const float* b_proj = (const float*)d_in[4];
    const float* gamma = (const float*)d_in[5];
    const float* beta = (const float*)d_in[6];
    float* out = (float*)d_out;

    gn_kernel<<<BATCH * NGROUP, 256>>>(x, gamma, beta);
    mm_kernel<0><<<dim3(HWTOK / 64, (3 * CHN) / 64, BATCH), 256>>>(w_qkv, b_qkv, nullptr, nullptr);
    attn_kernel<<<dim3(BATCH * NHEAD, HWTOK / 64), 128>>>();
    mm_kernel<1><<<dim3(HWTOK / 64, CHN / 64, BATCH), 256>>>(w_proj, b_proj, x, out);
}

// round 2
// speedup vs baseline: 2.5644x; 2.5644x over previous
#include <cuda_runtime.h>
#include <math.h>
#include <stdint.h>

#define BATCH 2
#define CHN 256
#define NHEAD 8
#define HDIM 32
#define HWTOK 4096
#define NGROUP 32
#define CPG 8
#define GN_EPS 1e-5f

// scratch (static device arrays; allocation-free per harness rules)
__device__ float g_h[BATCH * CHN * HWTOK];        // groupnorm output   [b][c][t]
__device__ float g_qkv[BATCH * 3 * CHN * HWTOK];  // qkv                [b][o][t]
__device__ float g_ao[BATCH * CHN * HWTOK];       // attention output   [b][c][t]

// ---------------------------------------------------------------------------
// GroupNorm
// ---------------------------------------------------------------------------
__global__ __launch_bounds__(256) void gn_kernel(const float* __restrict__ x,
                                                 const float* __restrict__ gamma,
                                                 const float* __restrict__ beta) {
    int b = blockIdx.x / NGROUP;
    int g = blockIdx.x % NGROUP;
    const float* xg = x + ((size_t)b * CHN + g * CPG) * HWTOK;
    float* hg = g_h + ((size_t)b * CHN + g * CPG) * HWTOK;
    const int N = CPG * HWTOK;

    float s = 0.f, ss = 0.f;
    for (int i = threadIdx.x; i < N; i += 256) {
        float v = xg[i];
        s += v;
        ss += v * v;
    }
#pragma unroll
    for (int o = 16; o; o >>= 1) {
        s += __shfl_xor_sync(0xffffffffu, s, o);
        ss += __shfl_xor_sync(0xffffffffu, ss, o);
    }
    __shared__ float red0[8], red1[8];
    int wid = threadIdx.x >> 5, lid = threadIdx.x & 31;
    if (lid == 0) { red0[wid] = s; red1[wid] = ss; }
    __syncthreads();
    __shared__ float s_mean, s_rstd;
    if (threadIdx.x == 0) {
        float S = 0.f, SS = 0.f;
        for (int w = 0; w < 8; w++) { S += red0[w]; SS += red1[w]; }
        float mean = S / (float)N;
        float var = SS / (float)N - mean * mean;
        s_mean = mean;
        s_rstd = rsqrtf(var + GN_EPS);
    }
    __syncthreads();
    float mean = s_mean, rstd = s_rstd;
    for (int i = threadIdx.x; i < N; i += 256) {
        int c = g * CPG + i / HWTOK;
        hg[i] = (xg[i] - mean) * rstd * gamma[c] + beta[c];
    }
}

// ---------------------------------------------------------------------------
// 1x1-conv GEMM (SIMT, unchanged this round)
// ---------------------------------------------------------------------------
template <int MODE>
__global__ __launch_bounds__(256) void mm_kernel(const float* __restrict__ W,
                                                 const float* __restrict__ bias,
                                                 const float* __restrict__ resid,
                                                 float* __restrict__ outx) {
    const int OC = (MODE == 0) ? 3 * CHN : CHN;
    const float* Hin = (MODE == 0) ? g_h : g_ao;
    float* out = (MODE == 0) ? g_qkv : outx;

    int b = blockIdx.z;
    int tb = blockIdx.x * 64;
    int ob = blockIdx.y * 64;
    int tx = threadIdx.x & 15, ty = threadIdx.x >> 4;

    __shared__ float sW[16][65];
    __shared__ float sH[16][64];
    float acc[4][4] = {};
    const float* Hb = Hin + (size_t)b * CHN * HWTOK;

    for (int kb = 0; kb < CHN; kb += 16) {
#pragma unroll
        for (int it = 0; it < 4; it++) {
            int idx = threadIdx.x + it * 256;
            int o = idx >> 4, k = idx & 15;
            sW[k][o] = W[(size_t)(ob + o) * CHN + kb + k];
        }
#pragma unroll
        for (int it = 0; it < 4; it++) {
            int idx = threadIdx.x + it * 256;
            int k = idx >> 6, t = idx & 63;
            sH[k][t] = Hb[(size_t)(kb + k) * HWTOK + tb + t];
        }
        __syncthreads();
#pragma unroll
        for (int kk = 0; kk < 16; kk++) {
            float a[4], bb[4];
#pragma unroll
            for (int i = 0; i < 4; i++) a[i] = sW[kk][ty + 16 * i];
#pragma unroll
            for (int j = 0; j < 4; j++) bb[j] = sH[kk][tx + 16 * j];
#pragma unroll
            for (int i = 0; i < 4; i++)
#pragma unroll
                for (int j = 0; j < 4; j++) acc[i][j] += a[i] * bb[j];
        }
        __syncthreads();
    }
#pragma unroll
    for (int i = 0; i < 4; i++) {
        int o = ob + ty + 16 * i;
        float bi = bias[o];
#pragma unroll
        for (int j = 0; j < 4; j++) {
            int t = tb + tx + 16 * j;
            float v = acc[i][j] + bi;
            if (MODE == 1) v += resid[((size_t)b * CHN + o) * HWTOK + t];
            out[((size_t)b * OC + o) * HWTOK + t] = v;
        }
    }
}

// ---------------------------------------------------------------------------
// tf32 tensor-core flash attention.
// Block = 128 threads (4 warps), 128-query tile; each warp owns 32 query rows
// (2 m-tiles of m16n8k8). K/V chunk = 32 keys. Softmax fully in registers
// (quad shuffles). P relayout C->A via per-warp smem.
// ---------------------------------------------------------------------------
__device__ __forceinline__ uint32_t f2tf(float x) {
    uint32_t r;
    asm("cvt.rna.tf32.f32 %0, %1;" : "=r"(r) : "f"(x));
    return r;
}

__device__ __forceinline__ void mma_tf32(float* d, const uint32_t* a, const uint32_t* b) {
    asm volatile(
        "mma.sync.aligned.m16n8k8.row.col.f32.tf32.tf32.f32 "
        "{%0,%1,%2,%3}, {%4,%5,%6,%7}, {%8,%9}, {%0,%1,%2,%3};\n"
        : "+f"(d[0]), "+f"(d[1]), "+f"(d[2]), "+f"(d[3])
        : "r"(a[0]), "r"(a[1]), "r"(a[2]), "r"(a[3]), "r"(b[0]), "r"(b[1]));
}

__global__ __launch_bounds__(128) void attn_kernel() {
    __shared__ float sK[32][36];       // [d][key]
    __shared__ float sV[32][36];       // [d][key]
    __shared__ float sP[4][32][40];    // per-warp P [row][key]; reused as out stage [32][132]

    int tid = threadIdx.x;
    int warp = tid >> 5, lane = tid & 31;
    int q4 = lane >> 2, r4 = lane & 3;
    int bh = blockIdx.x;
    int b = bh >> 3, n = bh & 7;
    int qb = blockIdx.y * 128;
    int rbase = warp * 32;

    const float scale = 0.17677669529663687f;  // 1/sqrt(32)
    const float* Qp = g_qkv + ((size_t)b * 768 + n * HDIM) * HWTOK;
    const float* Kp = g_qkv + ((size_t)b * 768 + 256 + n * HDIM) * HWTOK;
    const float* Vp = g_qkv + ((size_t)b * 768 + 512 + n * HDIM) * HWTOK;

    // Q fragments, persistent in registers (pre-scaled, tf32-rounded)
    uint32_t qf[2][4][4];
#pragma unroll
    for (int mt = 0; mt < 2; mt++) {
        int row = qb + rbase + mt * 16 + q4;
#pragma unroll
        for (int kk = 0; kk < 4; kk++) {
            int d0 = kk * 8 + r4;
            qf[mt][kk][0] = f2tf(Qp[(size_t)d0 * HWTOK + row] * scale);
            qf[mt][kk][1] = f2tf(Qp[(size_t)d0 * HWTOK + row + 8] * scale);
            qf[mt][kk][2] = f2tf(Qp[(size_t)(d0 + 4) * HWTOK + row] * scale);
            qf[mt][kk][3] = f2tf(Qp[(size_t)(d0 + 4) * HWTOK + row + 8] * scale);
        }
    }

    float mrow[2][2] = {{-3.0e38f, -3.0e38f}, {-3.0e38f, -3.0e38f}};
    float lrow[2][2] = {{0.f, 0.f}, {0.f, 0.f}};
    float O[2][4][4] = {};

    for (int kc = 0; kc < HWTOK; kc += 32) {
        __syncthreads();  // previous chunk's frag reads done
#pragma unroll
        for (int it = 0; it < 8; it++) {
            int idx = tid + it * 128;
            int d = idx >> 5, c = idx & 31;
            sK[d][c] = Kp[(size_t)d * HWTOK + kc + c];
            sV[d][c] = Vp[(size_t)d * HWTOK + kc + c];
        }
        __syncthreads();

        // S = (Q*scale) K^T   [2 mtiles][4 ntiles]
        float S[2][4][4] = {};
#pragma unroll
        for (int kk = 0; kk < 4; kk++) {
#pragma unroll
            for (int nn = 0; nn < 4; nn++) {
                uint32_t kf[2];
                kf[0] = __float_as_uint(sK[kk * 8 + r4][nn * 8 + q4]);
                kf[1] = __float_as_uint(sK[kk * 8 + r4 + 4][nn * 8 + q4]);
                mma_tf32(S[0][nn], qf[0][kk], kf);
                mma_tf32(S[1][nn], qf[1][kk], kf);
            }
        }

        // online softmax, all in registers (rows are quad-local)
#pragma unroll
        for (int mt = 0; mt < 2; mt++) {
#pragma unroll
            for (int rh = 0; rh < 2; rh++) {
                float mx = -3.0e38f;
#pragma unroll
                for (int nn = 0; nn < 4; nn++) {
                    mx = fmaxf(mx, S[mt][nn][rh * 2]);
                    mx = fmaxf(mx, S[mt][nn][rh * 2 + 1]);
                }
                mx = fmaxf(mx, __shfl_xor_sync(0xffffffffu, mx, 1));
                mx = fmaxf(mx, __shfl_xor_sync(0xffffffffu, mx, 2));
                float mold = mrow[mt][rh];
                float mnew = fmaxf(mold, mx);
                float corr = __expf(mold - mnew);
                float ls = 0.f;
#pragma unroll
                for (int nn = 0; nn < 4; nn++) {
                    float p0 = __expf(S[mt][nn][rh * 2] - mnew);
                    float p1 = __expf(S[mt][nn][rh * 2 + 1] - mnew);
                    S[mt][nn][rh * 2] = p0;
                    S[mt][nn][rh * 2 + 1] = p1;
                    ls += p0 + p1;
                }
                ls += __shfl_xor_sync(0xffffffffu, ls, 1);
                ls += __shfl_xor_sync(0xffffffffu, ls, 2);
                lrow[mt][rh] = lrow[mt][rh] * corr + ls;
                mrow[mt][rh] = mnew;
#pragma unroll
                for (int nd = 0; nd < 4; nd++) {
                    O[mt][nd][rh * 2] *= corr;
                    O[mt][nd][rh * 2 + 1] *= corr;
                }
            }
        }

        // P -> per-warp smem (C layout -> A layout relay), tf32-rounded
        float(*sPw)[40] = sP[warp];
#pragma unroll
        for (int mt = 0; mt < 2; mt++) {
            int r0 = mt * 16 + q4;
#pragma unroll
            for (int nn = 0; nn < 4; nn++) {
                float2 lo = make_float2(__uint_as_float(f2tf(S[mt][nn][0])),
                                        __uint_as_float(f2tf(S[mt][nn][1])));
                float2 hi = make_float2(__uint_as_float(f2tf(S[mt][nn][2])),
                                        __uint_as_float(f2tf(S[mt][nn][3])));
                *(float2*)&sPw[r0][nn * 8 + 2 * r4] = lo;
                *(float2*)&sPw[r0 + 8][nn * 8 + 2 * r4] = hi;
            }
        }
        __syncwarp();

        // O += P V
#pragma unroll
        for (int kk = 0; kk < 4; kk++) {
            uint32_t vf[4][2];
#pragma unroll
            for (int nd = 0; nd < 4; nd++) {
                vf[nd][0] = __float_as_uint(sV[nd * 8 + q4][kk * 8 + r4]);
                vf[nd][1] = __float_as_uint(sV[nd * 8 + q4][kk * 8 + r4 + 4]);
            }
#pragma unroll
            for (int mt = 0; mt < 2; mt++) {
                uint32_t af[4];
                af[0] = __float_as_uint(sPw[mt * 16 + q4][kk * 8 + r4]);
                af[1] = __float_as_uint(sPw[mt * 16 + q4 + 8][kk * 8 + r4]);
                af[2] = __float_as_uint(sPw[mt * 16 + q4][kk * 8 + r4 + 4]);
                af[3] = __float_as_uint(sPw[mt * 16 + q4 + 8][kk * 8 + r4 + 4]);
#pragma unroll
                for (int nd = 0; nd < 4; nd++) mma_tf32(O[mt][nd], af, vf[nd]);
            }
        }
    }

    // epilogue: normalize, stage [d][row], coalesced store
    __syncthreads();
    float* sOut = &sP[0][0][0];  // [32][132]
#pragma unroll
    for (int mt = 0; mt < 2; mt++) {
#pragma unroll
        for (int rh = 0; rh < 2; rh++) {
            float inv = 1.f / lrow[mt][rh];
            int row = rbase + mt * 16 + q4 + rh * 8;
#pragma unroll
            for (int nd = 0; nd < 4; nd++) {
                sOut[(nd * 8 + 2 * r4) * 132 + row] = O[mt][nd][rh * 2] * inv;
                sOut[(nd * 8 + 2 * r4 + 1) * 132 + row] = O[mt][nd][rh * 2 + 1] * inv;
            }
        }
    }
    __syncthreads();
    float* aop = g_ao + ((size_t)b * CHN + n * HDIM) * HWTOK;
#pragma unroll
    for (int it = 0; it < 32; it++) {
        int idx = tid + it * 128;
        int d = idx >> 7, r = idx & 127;
        aop[(size_t)d * HWTOK + qb + r] = sOut[d * 132 + r];
    }
}

// ---------------------------------------------------------------------------
extern "C" void kernel_launch(void* const* d_in, const int* in_sizes, int n_in,
                              void* d_out, int out_size) {
    const float* x = (const float*)d_in[0];
    const float* w_qkv = (const float*)d_in[1];
    const float* b_qkv = (const float*)d_in[2];
    const float* w_proj = (const float*)d_in[3];
    const float* b_proj = (const float*)d_in[4];
    const float* gamma = (const float*)d_in[5];
    const float* beta = (const float*)d_in[6];
    float* out = (float*)d_out;

    gn_kernel<<<BATCH * NGROUP, 256>>>(x, gamma, beta);
    mm_kernel<0><<<dim3(HWTOK / 64, (3 * CHN) / 64, BATCH), 256>>>(w_qkv, b_qkv, nullptr, nullptr);
    attn_kernel<<<dim3(BATCH * NHEAD, HWTOK / 128), 128>>>();
    mm_kernel<1><<<dim3(HWTOK / 64, CHN / 64, BATCH), 256>>>(w_proj, b_proj, x, out);
}

// round 4
// speedup vs baseline: 4.2578x; 1.6603x over previous
#include <cuda_runtime.h>
#include <math.h>
#include <stdint.h>

#define BATCH 2
#define CHN 256
#define NHEAD 8
#define HDIM 32
#define HWTOK 4096
#define NGROUP 32
#define GN_EPS 1e-5f

// scratch (static device arrays; allocation-free per harness rules)
__device__ float g_qkv[BATCH * 3 * CHN * HWTOK];  // qkv [b][o][t]
__device__ float g_ao[BATCH * CHN * HWTOK];       // attention output [b][c][t]
__device__ float g_mean[BATCH * NGROUP];
__device__ float g_rstd[BATCH * NGROUP];

__device__ __forceinline__ uint32_t f2tf(float x) {
    uint32_t r;
    asm("cvt.rna.tf32.f32 %0, %1;" : "=r"(r) : "f"(x));
    return r;
}
__device__ __forceinline__ float ex2(float x) {
    float y;
    asm("ex2.approx.f32 %0, %1;" : "=f"(y) : "f"(x));
    return y;
}
__device__ __forceinline__ void mma_tf32(float* d, const uint32_t* a, const uint32_t* b) {
    asm volatile(
        "mma.sync.aligned.m16n8k8.row.col.f32.tf32.tf32.f32 "
        "{%0,%1,%2,%3}, {%4,%5,%6,%7}, {%8,%9}, {%0,%1,%2,%3};\n"
        : "+f"(d[0]), "+f"(d[1]), "+f"(d[2]), "+f"(d[3])
        : "r"(a[0]), "r"(a[1]), "r"(a[2]), "r"(a[3]), "r"(b[0]), "r"(b[1]));
}
__device__ __forceinline__ void cp16(void* smem_dst, const void* gsrc) {
    uint32_t d = (uint32_t)__cvta_generic_to_shared(smem_dst);
    asm volatile("cp.async.cg.shared.global [%0], [%1], 16;\n" ::"r"(d), "l"(gsrc));
}
__device__ __forceinline__ void cp_commit() { asm volatile("cp.async.commit_group;\n"); }
template <int N>
__device__ __forceinline__ void cp_wait() { asm volatile("cp.async.wait_group %0;\n" ::"n"(N)); }

// ---------------------------------------------------------------------------
// GroupNorm statistics only (normalization fused into mm_tc<0>)
// ---------------------------------------------------------------------------
__global__ __launch_bounds__(256) void gn_stats(const float* __restrict__ x) {
    int b = blockIdx.x / NGROUP;
    int g = blockIdx.x % NGROUP;
    const float* xg = x + ((size_t)b * CHN + g * 8) * HWTOK;
    const int N = 8 * HWTOK;
    float s = 0.f, ss = 0.f;
    for (int i = threadIdx.x; i < N; i += 256) {
        float v = xg[i];
        s += v;
        ss += v * v;
    }
#pragma unroll
    for (int o = 16; o; o >>= 1) {
        s += __shfl_xor_sync(0xffffffffu, s, o);
        ss += __shfl_xor_sync(0xffffffffu, ss, o);
    }
    __shared__ float red0[8], red1[8];
    int wid = threadIdx.x >> 5, lid = threadIdx.x & 31;
    if (lid == 0) { red0[wid] = s; red1[wid] = ss; }
    __syncthreads();
    if (threadIdx.x == 0) {
        float S = 0.f, SS = 0.f;
        for (int w = 0; w < 8; w++) { S += red0[w]; SS += red1[w]; }
        float mean = S / (float)N;
        float var = SS / (float)N - mean * mean;
        g_mean[blockIdx.x] = mean;
        g_rstd[blockIdx.x] = rsqrtf(var + GN_EPS);
    }
}

// ---------------------------------------------------------------------------
// tf32 tensor-core 1x1-conv GEMM. Block 128 thr (4 warps), tile 64(o) x 64(t).
// MODE 0: Hin = x (external) with fused GroupNorm affine, out = g_qkv (OC=768).
// MODE 1: Hin = g_ao (device symbol), out = external, += resid (OC=256).
// ---------------------------------------------------------------------------
template <int MODE>
__global__ __launch_bounds__(128) void mm_tc(const float* __restrict__ W,
                                             const float* __restrict__ bias,
                                             const float* __restrict__ Hext,
                                             const float* __restrict__ resid,
                                             const float* __restrict__ gamma,
                                             const float* __restrict__ beta,
                                             float* __restrict__ outext) {
    const int OC = (MODE == 0) ? 3 * CHN : CHN;
    const float* Hsrc = (MODE == 0) ? Hext : g_ao;
    float* out = (MODE == 0) ? g_qkv : outext;

    __shared__ float sW[64][36];   // [o][k]
    __shared__ float sH[32][72];   // [k][t]
    __shared__ float sA[256], sB[256];

    int b = blockIdx.z;
    int tb = blockIdx.x * 64, ob = blockIdx.y * 64;
    int tid = threadIdx.x, warp = tid >> 5, lane = tid & 31;
    int q4 = lane >> 2, r4 = lane & 3;
    int m0 = (warp & 1) * 32, n0 = (warp >> 1) * 32;
    const float* Hb = Hsrc + (size_t)b * CHN * HWTOK;

    if (MODE == 0) {
        for (int c = tid; c < 256; c += 128) {
            int g = c >> 3;
            float a = g_rstd[b * NGROUP + g] * gamma[c];
            sA[c] = a;
            sB[c] = beta[c] - g_mean[b * NGROUP + g] * a;
        }
    }
    __syncthreads();

    float acc[2][4][4] = {};
    for (int kb = 0; kb < CHN; kb += 32) {
#pragma unroll
        for (int it = 0; it < 4; it++) {
            int idx4 = tid + it * 128;
            int o = idx4 >> 3, k4 = idx4 & 7;
            float4 wv = *(const float4*)&W[(size_t)(ob + o) * CHN + kb + 4 * k4];
            wv.x = __uint_as_float(f2tf(wv.x));
            wv.y = __uint_as_float(f2tf(wv.y));
            wv.z = __uint_as_float(f2tf(wv.z));
            wv.w = __uint_as_float(f2tf(wv.w));
            *(float4*)&sW[o][4 * k4] = wv;
        }
#pragma unroll
        for (int it = 0; it < 4; it++) {
            int idx4 = tid + it * 128;
            int k = idx4 >> 4, t4 = idx4 & 15;
            int c = kb + k;
            float4 hv = *(const float4*)&Hb[(size_t)c * HWTOK + tb + 4 * t4];
            if (MODE == 0) {
                float a = sA[c], sh = sB[c];
                hv.x = fmaf(hv.x, a, sh);
                hv.y = fmaf(hv.y, a, sh);
                hv.z = fmaf(hv.z, a, sh);
                hv.w = fmaf(hv.w, a, sh);
            }
            *(float4*)&sH[k][4 * t4] = hv;
        }
        __syncthreads();
#pragma unroll
        for (int kk = 0; kk < 4; kk++) {
            uint32_t af[2][4], bf[4][2];
#pragma unroll
            for (int mt = 0; mt < 2; mt++) {
                int r0 = m0 + mt * 16 + q4;
                af[mt][0] = __float_as_uint(sW[r0][kk * 8 + r4]);
                af[mt][1] = __float_as_uint(sW[r0 + 8][kk * 8 + r4]);
                af[mt][2] = __float_as_uint(sW[r0][kk * 8 + r4 + 4]);
                af[mt][3] = __float_as_uint(sW[r0 + 8][kk * 8 + r4 + 4]);
            }
#pragma unroll
            for (int nn = 0; nn < 4; nn++) {
                bf[nn][0] = __float_as_uint(sH[kk * 8 + r4][n0 + nn * 8 + q4]);
                bf[nn][1] = __float_as_uint(sH[kk * 8 + r4 + 4][n0 + nn * 8 + q4]);
            }
#pragma unroll
            for (int mt = 0; mt < 2; mt++)
#pragma unroll
                for (int nn = 0; nn < 4; nn++) mma_tf32(acc[mt][nn], af[mt], bf[nn]);
        }
        __syncthreads();
    }
#pragma unroll
    for (int mt = 0; mt < 2; mt++) {
        int o = ob + m0 + mt * 16 + q4;
        float bi0 = bias[o], bi1 = bias[o + 8];
#pragma unroll
        for (int nn = 0; nn < 4; nn++) {
            int t = tb + n0 + nn * 8 + 2 * r4;
            float2 v0 = make_float2(acc[mt][nn][0] + bi0, acc[mt][nn][1] + bi0);
            float2 v1 = make_float2(acc[mt][nn][2] + bi1, acc[mt][nn][3] + bi1);
            if (MODE == 1) {
                float2 r0 = *(const float2*)&resid[((size_t)b * CHN + o) * HWTOK + t];
                float2 r1 = *(const float2*)&resid[((size_t)b * CHN + o + 8) * HWTOK + t];
                v0.x += r0.x; v0.y += r0.y;
                v1.x += r1.x; v1.y += r1.y;
            }
            *(float2*)&out[((size_t)b * OC + o) * HWTOK + t] = v0;
            *(float2*)&out[((size_t)b * OC + o + 8) * HWTOK + t] = v1;
        }
    }
}

// ---------------------------------------------------------------------------
// tf32 flash attention: 128-query tile, 4 warps x 32 rows, 64-key chunks,
// 2-stage cp.async pipeline, log2-domain online softmax (bare ex2).
// Dynamic smem: sK[2][32][72] | sV[2][32][68] | sP[4][32][68]
// ---------------------------------------------------------------------------
__global__ __launch_bounds__(128) void attn_kernel() {
    extern __shared__ float dsm[];
    float(*sK)[32][72] = (float(*)[32][72])dsm;
    float(*sV)[32][68] = (float(*)[32][68])(dsm + 2 * 32 * 72);
    float(*sP)[32][68] = (float(*)[32][68])(dsm + 2 * 32 * 72 + 2 * 32 * 68);

    int tid = threadIdx.x;
    int warp = tid >> 5, lane = tid & 31;
    int q4 = lane >> 2, r4 = lane & 3;
    int bh = blockIdx.x;
    int b = bh >> 3, n = bh & 7;
    int qb = blockIdx.y * 128;
    int rbase = warp * 32;

    // 1/sqrt(32) * log2(e): softmax runs in log2 domain
    const float SC = 0.25501333583834134f;
    const float* Qp = g_qkv + ((size_t)b * 768 + n * HDIM) * HWTOK;
    const float* Kp = g_qkv + ((size_t)b * 768 + 256 + n * HDIM) * HWTOK;
    const float* Vp = g_qkv + ((size_t)b * 768 + 512 + n * HDIM) * HWTOK;

    // Q fragments persistent in registers
    uint32_t qf[2][4][4];
#pragma unroll
    for (int mt = 0; mt < 2; mt++) {
        int row = qb + rbase + mt * 16 + q4;
#pragma unroll
        for (int kk = 0; kk < 4; kk++) {
            int d0 = kk * 8 + r4;
            qf[mt][kk][0] = f2tf(Qp[(size_t)d0 * HWTOK + row] * SC);
            qf[mt][kk][1] = f2tf(Qp[(size_t)d0 * HWTOK + row + 8] * SC);
            qf[mt][kk][2] = f2tf(Qp[(size_t)(d0 + 4) * HWTOK + row] * SC);
            qf[mt][kk][3] = f2tf(Qp[(size_t)(d0 + 4) * HWTOK + row + 8] * SC);
        }
    }

    float mrow[2][2] = {{-3.0e38f, -3.0e38f}, {-3.0e38f, -3.0e38f}};
    float lrow[2][2] = {{0.f, 0.f}, {0.f, 0.f}};
    float O[2][4][4] = {};

    // prologue load: chunk 0 into stage 0
    {
#pragma unroll
        for (int it = 0; it < 4; it++) {
            int idx4 = tid + it * 128;
            int d = idx4 >> 4, c4 = idx4 & 15;
            cp16(&sK[0][d][4 * c4], Kp + (size_t)d * HWTOK + 4 * c4);
            cp16(&sV[0][d][4 * c4], Vp + (size_t)d * HWTOK + 4 * c4);
        }
        cp_commit();
    }

    for (int ci = 0; ci < 64; ci++) {
        int st = ci & 1;
        __syncthreads();  // all warps done reading buf[st] from iter ci-2
        if (ci + 1 < 64) {
            int kc = (ci + 1) * 64;
#pragma unroll
            for (int it = 0; it < 4; it++) {
                int idx4 = tid + it * 128;
                int d = idx4 >> 4, c4 = idx4 & 15;
                cp16(&sK[st ^ 1][d][4 * c4], Kp + (size_t)d * HWTOK + kc + 4 * c4);
                cp16(&sV[st ^ 1][d][4 * c4], Vp + (size_t)d * HWTOK + kc + 4 * c4);
            }
        }
        cp_commit();      // (possibly empty) group
        cp_wait<1>();     // chunk ci complete
        __syncthreads();  // visibility

        // S = Q K^T  [2 mtiles][8 ntiles]
        float S[2][8][4] = {};
#pragma unroll
        for (int kk = 0; kk < 4; kk++) {
#pragma unroll
            for (int nn = 0; nn < 8; nn++) {
                uint32_t kf[2];
                kf[0] = __float_as_uint(sK[st][kk * 8 + r4][nn * 8 + q4]);
                kf[1] = __float_as_uint(sK[st][kk * 8 + r4 + 4][nn * 8 + q4]);
                mma_tf32(S[0][nn], qf[0][kk], kf);
                mma_tf32(S[1][nn], qf[1][kk], kf);
            }
        }

        // online softmax in registers (log2 domain)
#pragma unroll
        for (int mt = 0; mt < 2; mt++) {
#pragma unroll
            for (int rh = 0; rh < 2; rh++) {
                float mx = -3.0e38f;
#pragma unroll
                for (int nn = 0; nn < 8; nn++) {
                    mx = fmaxf(mx, S[mt][nn][rh * 2]);
                    mx = fmaxf(mx, S[mt][nn][rh * 2 + 1]);
                }
                mx = fmaxf(mx, __shfl_xor_sync(0xffffffffu, mx, 1));
                mx = fmaxf(mx, __shfl_xor_sync(0xffffffffu, mx, 2));
                float mold = mrow[mt][rh];
                float mnew = fmaxf(mold, mx);
                float corr = ex2(mold - mnew);
                float ls = 0.f;
#pragma unroll
                for (int nn = 0; nn < 8; nn++) {
                    float p0 = ex2(S[mt][nn][rh * 2] - mnew);
                    float p1 = ex2(S[mt][nn][rh * 2 + 1] - mnew);
                    S[mt][nn][rh * 2] = p0;
                    S[mt][nn][rh * 2 + 1] = p1;
                    ls += p0 + p1;
                }
                ls += __shfl_xor_sync(0xffffffffu, ls, 1);
                ls += __shfl_xor_sync(0xffffffffu, ls, 2);
                lrow[mt][rh] = lrow[mt][rh] * corr + ls;
                mrow[mt][rh] = mnew;
#pragma unroll
                for (int nd = 0; nd < 4; nd++) {
                    O[mt][nd][rh * 2] *= corr;
                    O[mt][nd][rh * 2 + 1] *= corr;
                }
            }
        }

        // P -> per-warp smem (C layout -> A layout)
        float(*sPw)[68] = sP[warp];
#pragma unroll
        for (int mt = 0; mt < 2; mt++) {
            int r0 = mt * 16 + q4;
#pragma unroll
            for (int nn = 0; nn < 8; nn++) {
                *(float2*)&sPw[r0][nn * 8 + 2 * r4] = make_float2(S[mt][nn][0], S[mt][nn][1]);
                *(float2*)&sPw[r0 + 8][nn * 8 + 2 * r4] = make_float2(S[mt][nn][2], S[mt][nn][3]);
            }
        }
        __syncwarp();

        // O += P V
#pragma unroll
        for (int kk = 0; kk < 8; kk++) {
            uint32_t vf[4][2];
#pragma unroll
            for (int nd = 0; nd < 4; nd++) {
                vf[nd][0] = __float_as_uint(sV[st][nd * 8 + q4][kk * 8 + r4]);
                vf[nd][1] = __float_as_uint(sV[st][nd * 8 + q4][kk * 8 + r4 + 4]);
            }
#pragma unroll
            for (int mt = 0; mt < 2; mt++) {
                uint32_t af[4];
                af[0] = __float_as_uint(sPw[mt * 16 + q4][kk * 8 + r4]);
                af[1] = __float_as_uint(sPw[mt * 16 + q4 + 8][kk * 8 + r4]);
                af[2] = __float_as_uint(sPw[mt * 16 + q4][kk * 8 + r4 + 4]);
                af[3] = __float_as_uint(sPw[mt * 16 + q4 + 8][kk * 8 + r4 + 4]);
#pragma unroll
                for (int nd = 0; nd < 4; nd++) mma_tf32(O[mt][nd], af, vf[nd]);
            }
        }
    }

    // epilogue: normalize, stage [d][row] via sP area, coalesced store
    __syncthreads();
    float* sOut = (float*)sP;  // [32][132]
#pragma unroll
    for (int mt = 0; mt < 2; mt++) {
#pragma unroll
        for (int rh = 0; rh < 2; rh++) {
            float inv = 1.f / lrow[mt][rh];
            int row = rbase + mt * 16 + q4 + rh * 8;
#pragma unroll
            for (int nd = 0; nd < 4; nd++) {
                sOut[(nd * 8 + 2 * r4) * 132 + row] = O[mt][nd][rh * 2] * inv;
                sOut[(nd * 8 + 2 * r4 + 1) * 132 + row] = O[mt][nd][rh * 2 + 1] * inv;
            }
        }
    }
    __syncthreads();
    float* aop = g_ao + ((size_t)b * CHN + n * HDIM) * HWTOK;
#pragma unroll
    for (int it = 0; it < 32; it++) {
        int idx = tid + it * 128;
        int d = idx >> 7, r = idx & 127;
        aop[(size_t)d * HWTOK + qb + r] = sOut[d * 132 + r];
    }
}

// ---------------------------------------------------------------------------
extern "C" void kernel_launch(void* const* d_in, const int* in_sizes, int n_in,
                              void* d_out, int out_size) {
    const float* x = (const float*)d_in[0];
    const float* w_qkv = (const float*)d_in[1];
    const float* b_qkv = (const float*)d_in[2];
    const float* w_proj = (const float*)d_in[3];
    const float* b_proj = (const float*)d_in[4];
    const float* gamma = (const float*)d_in[5];
    const float* beta = (const float*)d_in[6];
    float* out = (float*)d_out;

    const int ATTN_SMEM = (2 * 32 * 72 + 2 * 32 * 68 + 4 * 32 * 68) * 4;  // 70656
    static bool attr_set = false;
    if (!attr_set) {
        cudaFuncSetAttribute(attn_kernel, cudaFuncAttributeMaxDynamicSharedMemorySize, ATTN_SMEM);
        attr_set = true;
    }

    gn_stats<<<BATCH * NGROUP, 256>>>(x);
    mm_tc<0><<<dim3(HWTOK / 64, (3 * CHN) / 64, BATCH), 128>>>(w_qkv, b_qkv, x, nullptr,
                                                               gamma, beta, nullptr);
    attn_kernel<<<dim3(BATCH * NHEAD, HWTOK / 128), 128, ATTN_SMEM>>>();
    mm_tc<1><<<dim3(HWTOK / 64, CHN / 64, BATCH), 128>>>(w_proj, b_proj, nullptr, x,
                                                         nullptr, nullptr, out);
}

// round 5
// speedup vs baseline: 4.5183x; 1.0612x over previous
#include <cuda_runtime.h>
#include <math.h>
#include <stdint.h>

#define BATCH 2
#define CHN 256
#define NHEAD 8
#define HDIM 32
#define HWTOK 4096
#define NGROUP 32
#define GN_EPS 1e-5f

// scratch (static device arrays; allocation-free per harness rules)
__device__ float g_qkv[BATCH * 3 * CHN * HWTOK];  // qkv [b][o][t]
__device__ float g_ao[BATCH * CHN * HWTOK];       // attention output [b][c][t]
__device__ float g_mean[BATCH * NGROUP];
__device__ float g_rstd[BATCH * NGROUP];

__device__ __forceinline__ float ex2(float x) {
    float y;
    asm("ex2.approx.f32 %0, %1;" : "=f"(y) : "f"(x));
    return y;
}
__device__ __forceinline__ void mma_tf32(float* d, const uint32_t* a, const uint32_t* b) {
    asm volatile(
        "mma.sync.aligned.m16n8k8.row.col.f32.tf32.tf32.f32 "
        "{%0,%1,%2,%3}, {%4,%5,%6,%7}, {%8,%9}, {%0,%1,%2,%3};\n"
        : "+f"(d[0]), "+f"(d[1]), "+f"(d[2]), "+f"(d[3])
        : "r"(a[0]), "r"(a[1]), "r"(a[2]), "r"(a[3]), "r"(b[0]), "r"(b[1]));
}
__device__ __forceinline__ void cp16(void* smem_dst, const void* gsrc) {
    uint32_t d = (uint32_t)__cvta_generic_to_shared(smem_dst);
    asm volatile("cp.async.cg.shared.global [%0], [%1], 16;\n" ::"r"(d), "l"(gsrc));
}
__device__ __forceinline__ void cp_commit() { asm volatile("cp.async.commit_group;\n"); }
template <int N>
__device__ __forceinline__ void cp_wait() { asm volatile("cp.async.wait_group %0;\n" ::"n"(N)); }

// ---------------------------------------------------------------------------
// GroupNorm statistics only (normalization folded into mm_tc<0> fragments)
// ---------------------------------------------------------------------------
__global__ __launch_bounds__(256) void gn_stats(const float* __restrict__ x) {
    int b = blockIdx.x / NGROUP;
    int g = blockIdx.x % NGROUP;
    const float4* xg = (const float4*)(x + ((size_t)b * CHN + g * 8) * HWTOK);
    const int N4 = 8 * HWTOK / 4;
    float s = 0.f, ss = 0.f;
    for (int i = threadIdx.x; i < N4; i += 256) {
        float4 v = xg[i];
        s += v.x + v.y + v.z + v.w;
        ss += v.x * v.x + v.y * v.y + v.z * v.z + v.w * v.w;
    }
#pragma unroll
    for (int o = 16; o; o >>= 1) {
        s += __shfl_xor_sync(0xffffffffu, s, o);
        ss += __shfl_xor_sync(0xffffffffu, ss, o);
    }
    __shared__ float red0[8], red1[8];
    int wid = threadIdx.x >> 5, lid = threadIdx.x & 31;
    if (lid == 0) { red0[wid] = s; red1[wid] = ss; }
    __syncthreads();
    if (threadIdx.x == 0) {
        float S = 0.f, SS = 0.f;
        for (int w = 0; w < 8; w++) { S += red0[w]; SS += red1[w]; }
        const float N = 8.f * HWTOK;
        float mean = S / N;
        float var = SS / N - mean * mean;
        g_mean[blockIdx.x] = mean;
        g_rstd[blockIdx.x] = rsqrtf(var + GN_EPS);
    }
}

// ---------------------------------------------------------------------------
// tf32 tensor-core 1x1-conv GEMM, cp.async double-buffered, 1 barrier/ktile.
// Block 128 thr (4 warps), tile 64(o) x 64(t).
// MODE 0: Hin = x (external), GN affine applied at B-fragment build, out=g_qkv.
// MODE 1: Hin = g_ao, out = external, += resid.
// ---------------------------------------------------------------------------
template <int MODE>
__global__ __launch_bounds__(128) void mm_tc(const float* __restrict__ W,
                                             const float* __restrict__ bias,
                                             const float* __restrict__ Hext,
                                             const float* __restrict__ resid,
                                             const float* __restrict__ gamma,
                                             const float* __restrict__ beta,
                                             float* __restrict__ outext) {
    const int OC = (MODE == 0) ? 3 * CHN : CHN;
    const float* Hsrc = (MODE == 0) ? Hext : g_ao;
    float* out = (MODE == 0) ? g_qkv : outext;

    __shared__ float sW[2][64][36];  // [buf][o][k]  (36: 4q4+r4 conflict-free)
    __shared__ float sH[2][32][72];  // [buf][k][t]  (72: 8r4+q4 conflict-free)
    __shared__ float sA[256], sB[256];

    int b = blockIdx.z;
    int tb = blockIdx.x * 64, ob = blockIdx.y * 64;
    int tid = threadIdx.x, warp = tid >> 5, lane = tid & 31;
    int q4 = lane >> 2, r4 = lane & 3;
    int m0 = (warp & 1) * 32, n0 = (warp >> 1) * 32;
    const float* Hb = Hsrc + (size_t)b * CHN * HWTOK;

    // prologue prefetch: k-tile 0
#pragma unroll
    for (int it = 0; it < 4; it++) {
        int idx = tid + it * 128;
        int o = idx >> 3, c8 = idx & 7;
        cp16(&sW[0][o][c8 * 4], &W[(size_t)(ob + o) * CHN + c8 * 4]);
    }
#pragma unroll
    for (int it = 0; it < 4; it++) {
        int idx = tid + it * 128;
        int k = idx >> 4, c16 = idx & 15;
        cp16(&sH[0][k][c16 * 4], &Hb[(size_t)k * HWTOK + tb + c16 * 4]);
    }
    cp_commit();

    if (MODE == 0) {
        for (int c = tid; c < 256; c += 128) {
            int g = c >> 3;
            float a = g_rstd[b * NGROUP + g] * gamma[c];
            sA[c] = a;
            sB[c] = beta[c] - g_mean[b * NGROUP + g] * a;
        }
    }

    float acc[2][4][4] = {};
    for (int kt = 0; kt < 8; kt++) {
        int buf = kt & 1;
        cp_wait<0>();
        __syncthreads();
        if (kt < 7) {
            int kb = (kt + 1) * 32;
#pragma unroll
            for (int it = 0; it < 4; it++) {
                int idx = tid + it * 128;
                int o = idx >> 3, c8 = idx & 7;
                cp16(&sW[buf ^ 1][o][c8 * 4], &W[(size_t)(ob + o) * CHN + kb + c8 * 4]);
            }
#pragma unroll
            for (int it = 0; it < 4; it++) {
                int idx = tid + it * 128;
                int k = idx >> 4, c16 = idx & 15;
                cp16(&sH[buf ^ 1][k][c16 * 4], &Hb[(size_t)(kb + k) * HWTOK + tb + c16 * 4]);
            }
            cp_commit();
        }
#pragma unroll
        for (int kk = 0; kk < 4; kk++) {
            uint32_t af[2][4], bf[4][2];
#pragma unroll
            for (int mt = 0; mt < 2; mt++) {
                int r0 = m0 + mt * 16 + q4;
                af[mt][0] = __float_as_uint(sW[buf][r0][kk * 8 + r4]);
                af[mt][1] = __float_as_uint(sW[buf][r0 + 8][kk * 8 + r4]);
                af[mt][2] = __float_as_uint(sW[buf][r0][kk * 8 + r4 + 4]);
                af[mt][3] = __float_as_uint(sW[buf][r0 + 8][kk * 8 + r4 + 4]);
            }
            if (MODE == 0) {
                int c0 = kt * 32 + kk * 8 + r4;
                float a0 = sA[c0], b0 = sB[c0];
                float a1 = sA[c0 + 4], b1 = sB[c0 + 4];
#pragma unroll
                for (int nn = 0; nn < 4; nn++) {
                    bf[nn][0] = __float_as_uint(fmaf(sH[buf][kk * 8 + r4][n0 + nn * 8 + q4], a0, b0));
                    bf[nn][1] = __float_as_uint(fmaf(sH[buf][kk * 8 + r4 + 4][n0 + nn * 8 + q4], a1, b1));
                }
            } else {
#pragma unroll
                for (int nn = 0; nn < 4; nn++) {
                    bf[nn][0] = __float_as_uint(sH[buf][kk * 8 + r4][n0 + nn * 8 + q4]);
                    bf[nn][1] = __float_as_uint(sH[buf][kk * 8 + r4 + 4][n0 + nn * 8 + q4]);
                }
            }
#pragma unroll
            for (int mt = 0; mt < 2; mt++)
#pragma unroll
                for (int nn = 0; nn < 4; nn++) mma_tf32(acc[mt][nn], af[mt], bf[nn]);
        }
    }
#pragma unroll
    for (int mt = 0; mt < 2; mt++) {
        int o = ob + m0 + mt * 16 + q4;
        float bi0 = bias[o], bi1 = bias[o + 8];
#pragma unroll
        for (int nn = 0; nn < 4; nn++) {
            int t = tb + n0 + nn * 8 + 2 * r4;
            float2 v0 = make_float2(acc[mt][nn][0] + bi0, acc[mt][nn][1] + bi0);
            float2 v1 = make_float2(acc[mt][nn][2] + bi1, acc[mt][nn][3] + bi1);
            if (MODE == 1) {
                float2 r0 = *(const float2*)&resid[((size_t)b * CHN + o) * HWTOK + t];
                float2 r1 = *(const float2*)&resid[((size_t)b * CHN + o + 8) * HWTOK + t];
                v0.x += r0.x; v0.y += r0.y;
                v1.x += r1.x; v1.y += r1.y;
            }
            *(float2*)&out[((size_t)b * OC + o) * HWTOK + t] = v0;
            *(float2*)&out[((size_t)b * OC + o + 8) * HWTOK + t] = v1;
        }
    }
}

// ---------------------------------------------------------------------------
// tf32 flash attention: 128-query tile, 4 warps x 32 rows, 32-key chunks,
// 2-stage cp.async pipeline with ONE barrier per chunk, log2-domain softmax,
// register-shuffle P transpose (C-frag -> A-frag, no smem round trip).
// Static smem 20.5KB; __launch_bounds__(128,4) -> 4 blocks/SM, single wave.
// ---------------------------------------------------------------------------
__global__ __launch_bounds__(128, 4) void attn_kernel() {
    __shared__ float dsm[5120];  // sK[2][32][40] | sV[2][32][40]; epi reuses as [32][132]
    float(*sK)[32][40] = (float(*)[32][40])dsm;
    float(*sV)[32][40] = (float(*)[32][40])(dsm + 2 * 32 * 40);

    int tid = threadIdx.x;
    int warp = tid >> 5, lane = tid & 31;
    int q4 = lane >> 2, r4 = lane & 3;
    int bh = blockIdx.x;
    int b = bh >> 3, n = bh & 7;
    int qb = blockIdx.y * 128;
    int rbase = warp * 32;

    const float SC = 0.25501333583834134f;  // (1/sqrt(32)) * log2(e)
    const float* Qp = g_qkv + ((size_t)b * 768 + n * HDIM) * HWTOK;
    const float* Kp = g_qkv + ((size_t)b * 768 + 256 + n * HDIM) * HWTOK;
    const float* Vp = g_qkv + ((size_t)b * 768 + 512 + n * HDIM) * HWTOK;

    // prologue: prefetch chunk 0 into buf 0
#pragma unroll
    for (int it = 0; it < 2; it++) {
        int idx = tid + it * 128;
        int d = idx >> 3, c8 = idx & 7;
        cp16(&sK[0][d][c8 * 4], Kp + (size_t)d * HWTOK + c8 * 4);
        cp16(&sV[0][d][c8 * 4], Vp + (size_t)d * HWTOK + c8 * 4);
    }
    cp_commit();

    // Q fragments persistent in registers (pre-scaled into log2 domain)
    uint32_t qf[2][4][4];
#pragma unroll
    for (int mt = 0; mt < 2; mt++) {
        int row = qb + rbase + mt * 16 + q4;
#pragma unroll
        for (int kk = 0; kk < 4; kk++) {
            int d0 = kk * 8 + r4;
            qf[mt][kk][0] = __float_as_uint(Qp[(size_t)d0 * HWTOK + row] * SC);
            qf[mt][kk][1] = __float_as_uint(Qp[(size_t)d0 * HWTOK + row + 8] * SC);
            qf[mt][kk][2] = __float_as_uint(Qp[(size_t)(d0 + 4) * HWTOK + row] * SC);
            qf[mt][kk][3] = __float_as_uint(Qp[(size_t)(d0 + 4) * HWTOK + row + 8] * SC);
        }
    }

    float mrow[2][2] = {{-3.0e38f, -3.0e38f}, {-3.0e38f, -3.0e38f}};
    float lrow[2][2] = {{0.f, 0.f}, {0.f, 0.f}};
    float O[2][4][4] = {};

    const int src_a = q4 * 4 + (r4 >> 1);
    const int src_b = src_a + 2;
    const bool pe = (r4 & 1);

    for (int ci = 0; ci < 128; ci++) {
        int st = ci & 1;
        cp_wait<0>();     // chunk ci data (this thread's copies) landed
        __syncthreads();  // all threads' copies visible; prior reads of buf st^1 done
        if (ci + 1 < 128) {
            int kc = (ci + 1) * 32;
#pragma unroll
            for (int it = 0; it < 2; it++) {
                int idx = tid + it * 128;
                int d = idx >> 3, c8 = idx & 7;
                cp16(&sK[st ^ 1][d][c8 * 4], Kp + (size_t)d * HWTOK + kc + c8 * 4);
                cp16(&sV[st ^ 1][d][c8 * 4], Vp + (size_t)d * HWTOK + kc + c8 * 4);
            }
            cp_commit();
        }

        // S = Q K^T  [2 mtiles][4 ntiles]
        float S[2][4][4] = {};
#pragma unroll
        for (int kk = 0; kk < 4; kk++) {
#pragma unroll
            for (int nn = 0; nn < 4; nn++) {
                uint32_t kf[2];
                kf[0] = __float_as_uint(sK[st][kk * 8 + r4][nn * 8 + q4]);
                kf[1] = __float_as_uint(sK[st][kk * 8 + r4 + 4][nn * 8 + q4]);
                mma_tf32(S[0][nn], qf[0][kk], kf);
                mma_tf32(S[1][nn], qf[1][kk], kf);
            }
        }

        // online softmax in registers (log2 domain)
#pragma unroll
        for (int mt = 0; mt < 2; mt++) {
#pragma unroll
            for (int rh = 0; rh < 2; rh++) {
                float mx = -3.0e38f;
#pragma unroll
                for (int nn = 0; nn < 4; nn++) {
                    mx = fmaxf(mx, S[mt][nn][rh * 2]);
                    mx = fmaxf(mx, S[mt][nn][rh * 2 + 1]);
                }
                mx = fmaxf(mx, __shfl_xor_sync(0xffffffffu, mx, 1));
                mx = fmaxf(mx, __shfl_xor_sync(0xffffffffu, mx, 2));
                float mold = mrow[mt][rh];
                float mnew = fmaxf(mold, mx);
                float corr = ex2(mold - mnew);
                float ls = 0.f;
#pragma unroll
                for (int nn = 0; nn < 4; nn++) {
                    float p0 = ex2(S[mt][nn][rh * 2] - mnew);
                    float p1 = ex2(S[mt][nn][rh * 2 + 1] - mnew);
                    S[mt][nn][rh * 2] = p0;
                    S[mt][nn][rh * 2 + 1] = p1;
                    ls += p0 + p1;
                }
                ls += __shfl_xor_sync(0xffffffffu, ls, 1);
                ls += __shfl_xor_sync(0xffffffffu, ls, 2);
                lrow[mt][rh] = lrow[mt][rh] * corr + ls;
                mrow[mt][rh] = mnew;
#pragma unroll
                for (int nd = 0; nd < 4; nd++) {
                    O[mt][nd][rh * 2] *= corr;
                    O[mt][nd][rh * 2 + 1] *= corr;
                }
            }
        }

        // O += P V : A-fragments via register shuffles (C->A relayout)
#pragma unroll
        for (int kk = 0; kk < 4; kk++) {
            uint32_t vf[4][2];
#pragma unroll
            for (int nd = 0; nd < 4; nd++) {
                vf[nd][0] = __float_as_uint(sV[st][nd * 8 + q4][kk * 8 + r4]);
                vf[nd][1] = __float_as_uint(sV[st][nd * 8 + q4][kk * 8 + r4 + 4]);
            }
#pragma unroll
            for (int mt = 0; mt < 2; mt++) {
                float e0 = __shfl_sync(0xffffffffu, S[mt][kk][0], src_a);
                float e1 = __shfl_sync(0xffffffffu, S[mt][kk][1], src_a);
                float e2 = __shfl_sync(0xffffffffu, S[mt][kk][2], src_a);
                float e3 = __shfl_sync(0xffffffffu, S[mt][kk][3], src_a);
                float f0 = __shfl_sync(0xffffffffu, S[mt][kk][0], src_b);
                float f1 = __shfl_sync(0xffffffffu, S[mt][kk][1], src_b);
                float f2 = __shfl_sync(0xffffffffu, S[mt][kk][2], src_b);
                float f3 = __shfl_sync(0xffffffffu, S[mt][kk][3], src_b);
                uint32_t af[4];
                af[0] = __float_as_uint(pe ? e1 : e0);
                af[1] = __float_as_uint(pe ? e3 : e2);
                af[2] = __float_as_uint(pe ? f1 : f0);
                af[3] = __float_as_uint(pe ? f3 : f2);
#pragma unroll
                for (int nd = 0; nd < 4; nd++) mma_tf32(O[mt][nd], af, vf[nd]);
            }
        }
    }

    // epilogue: normalize, stage [d][row] via smem, coalesced store
    __syncthreads();
    float* sOut = dsm;  // [32][132]
#pragma unroll
    for (int mt = 0; mt < 2; mt++) {
#pragma unroll
        for (int rh = 0; rh < 2; rh++) {
            float inv = 1.f / lrow[mt][rh];
            int row = rbase + mt * 16 + q4 + rh * 8;
#pragma unroll
            for (int nd = 0; nd < 4; nd++) {
                sOut[(nd * 8 + 2 * r4) * 132 + row] = O[mt][nd][rh * 2] * inv;
                sOut[(nd * 8 + 2 * r4 + 1) * 132 + row] = O[mt][nd][rh * 2 + 1] * inv;
            }
        }
    }
    __syncthreads();
    float* aop = g_ao + ((size_t)b * CHN + n * HDIM) * HWTOK;
#pragma unroll
    for (int it = 0; it < 32; it++) {
        int idx = tid + it * 128;
        int d = idx >> 7, r = idx & 127;
        aop[(size_t)d * HWTOK + qb + r] = sOut[d * 132 + r];
    }
}

// ---------------------------------------------------------------------------
extern "C" void kernel_launch(void* const* d_in, const int* in_sizes, int n_in,
                              void* d_out, int out_size) {
    const float* x = (const float*)d_in[0];
    const float* w_qkv = (const float*)d_in[1];
    const float* b_qkv = (const float*)d_in[2];
    const float* w_proj = (const float*)d_in[3];
    const float* b_proj = (const float*)d_in[4];
    const float* gamma = (const float*)d_in[5];
    const float* beta = (const float*)d_in[6];
    float* out = (float*)d_out;

    gn_stats<<<BATCH * NGROUP, 256>>>(x);
    mm_tc<0><<<dim3(HWTOK / 64, (3 * CHN) / 64, BATCH), 128>>>(w_qkv, b_qkv, x, nullptr,
                                                               gamma, beta, nullptr);
    attn_kernel<<<dim3(BATCH * NHEAD, HWTOK / 128), 128>>>();
    mm_tc<1><<<dim3(HWTOK / 64, CHN / 64, BATCH), 128>>>(w_proj, b_proj, nullptr, x,
                                                         nullptr, nullptr, out);
}

// round 7
// speedup vs baseline: 5.0596x; 1.1198x over previous
#include <cuda_runtime.h>
#include <math.h>
#include <stdint.h>

#define BATCH 2
#define CHN 256
#define NHEAD 8
#define HDIM 32
#define HWTOK 4096
#define NGROUP 32
#define GN_EPS 1e-5f

// scratch (static device arrays; allocation-free per harness rules)
__device__ float g_qkv[BATCH * 3 * CHN * HWTOK];  // qkv [b][o][t]
__device__ float g_ao[BATCH * CHN * HWTOK];       // attention output [b][c][t]
__device__ float g_mean[BATCH * NGROUP];
__device__ float g_rstd[BATCH * NGROUP];

__device__ __forceinline__ float ex2(float x) {
    float y;
    asm("ex2.approx.f32 %0, %1;" : "=f"(y) : "f"(x));
    return y;
}
__device__ __forceinline__ void mma_tf32(float* d, const uint32_t* a, const uint32_t* b) {
    asm volatile(
        "mma.sync.aligned.m16n8k8.row.col.f32.tf32.tf32.f32 "
        "{%0,%1,%2,%3}, {%4,%5,%6,%7}, {%8,%9}, {%0,%1,%2,%3};\n"
        : "+f"(d[0]), "+f"(d[1]), "+f"(d[2]), "+f"(d[3])
        : "r"(a[0]), "r"(a[1]), "r"(a[2]), "r"(a[3]), "r"(b[0]), "r"(b[1]));
}
__device__ __forceinline__ void cp16(void* smem_dst, const void* gsrc) {
    uint32_t d = (uint32_t)__cvta_generic_to_shared(smem_dst);
    asm volatile("cp.async.cg.shared.global [%0], [%1], 16;\n" ::"r"(d), "l"(gsrc));
}
__device__ __forceinline__ void cp_commit() { asm volatile("cp.async.commit_group;\n"); }
template <int N>
__device__ __forceinline__ void cp_wait() { asm volatile("cp.async.wait_group %0;\n" ::"n"(N)); }

// ---------------------------------------------------------------------------
// GroupNorm statistics only (normalization folded into mm_tc<0> fragments)
// ---------------------------------------------------------------------------
__global__ __launch_bounds__(256) void gn_stats(const float* __restrict__ x) {
    int b = blockIdx.x / NGROUP;
    int g = blockIdx.x % NGROUP;
    const float4* xg = (const float4*)(x + ((size_t)b * CHN + g * 8) * HWTOK);
    const int N4 = 8 * HWTOK / 4;
    float s = 0.f, ss = 0.f;
    for (int i = threadIdx.x; i < N4; i += 256) {
        float4 v = xg[i];
        s += v.x + v.y + v.z + v.w;
        ss += v.x * v.x + v.y * v.y + v.z * v.z + v.w * v.w;
    }
#pragma unroll
    for (int o = 16; o; o >>= 1) {
        s += __shfl_xor_sync(0xffffffffu, s, o);
        ss += __shfl_xor_sync(0xffffffffu, ss, o);
    }
    __shared__ float red0[8], red1[8];
    int wid = threadIdx.x >> 5, lid = threadIdx.x & 31;
    if (lid == 0) { red0[wid] = s; red1[wid] = ss; }
    __syncthreads();
    if (threadIdx.x == 0) {
        float S = 0.f, SS = 0.f;
        for (int w = 0; w < 8; w++) { S += red0[w]; SS += red1[w]; }
        const float N = 8.f * HWTOK;
        float mean = S / N;
        float var = SS / N - mean * mean;
        g_mean[blockIdx.x] = mean;
        g_rstd[blockIdx.x] = rsqrtf(var + GN_EPS);
    }
}

// ---------------------------------------------------------------------------
// tf32 tensor-core 1x1-conv GEMM, cp.async double-buffered, 1 barrier/ktile.
// Block 256 thr (8 warps as 2m x 4n), tile 64(o) x 128(t).
// MODE 0: Hin = x, GN affine applied at B-fragment build, out = g_qkv.
// MODE 1: Hin = g_ao, out = external, += resid.
// Dynamic smem: sW[2][64][36] | sH[2][32][136]  (53248 B)
// ---------------------------------------------------------------------------
template <int MODE>
__global__ __launch_bounds__(256) void mm_tc(const float* __restrict__ W,
                                             const float* __restrict__ bias,
                                             const float* __restrict__ Hext,
                                             const float* __restrict__ resid,
                                             const float* __restrict__ gamma,
                                             const float* __restrict__ beta,
                                             float* __restrict__ outext) {
    const int OC = (MODE == 0) ? 3 * CHN : CHN;
    const float* Hsrc = (MODE == 0) ? Hext : g_ao;
    float* out = (MODE == 0) ? g_qkv : outext;

    extern __shared__ float dynsm[];
    float(*sW)[64][36] = (float(*)[64][36])dynsm;                 // [buf][o][k]
    float(*sH)[32][136] = (float(*)[32][136])(dynsm + 2 * 64 * 36);  // [buf][k][t]
    __shared__ float sA[256], sB[256];

    int b = blockIdx.z;
    int tb = blockIdx.x * 128, ob = blockIdx.y * 64;
    int tid = threadIdx.x, warp = tid >> 5, lane = tid & 31;
    int q4 = lane >> 2, r4 = lane & 3;
    int m0 = (warp & 1) * 32, n0 = (warp >> 1) * 32;
    const float* Hb = Hsrc + (size_t)b * CHN * HWTOK;

    // prologue prefetch: k-tile 0
#pragma unroll
    for (int it = 0; it < 2; it++) {
        int idx = tid + it * 256;
        int o = idx >> 3, c8 = idx & 7;
        cp16(&sW[0][o][c8 * 4], &W[(size_t)(ob + o) * CHN + c8 * 4]);
    }
#pragma unroll
    for (int it = 0; it < 4; it++) {
        int idx = tid + it * 256;
        int k = idx >> 5, c32 = idx & 31;
        cp16(&sH[0][k][c32 * 4], &Hb[(size_t)k * HWTOK + tb + c32 * 4]);
    }
    cp_commit();

    if (MODE == 0) {
        for (int c = tid; c < 256; c += 256) {
            int g = c >> 3;
            float a = g_rstd[b * NGROUP + g] * gamma[c];
            sA[c] = a;
            sB[c] = beta[c] - g_mean[b * NGROUP + g] * a;
        }
    }

    float acc[2][4][4] = {};
    for (int kt = 0; kt < 8; kt++) {
        int buf = kt & 1;
        cp_wait<0>();
        __syncthreads();
        if (kt < 7) {
            int kb = (kt + 1) * 32;
#pragma unroll
            for (int it = 0; it < 2; it++) {
                int idx = tid + it * 256;
                int o = idx >> 3, c8 = idx & 7;
                cp16(&sW[buf ^ 1][o][c8 * 4], &W[(size_t)(ob + o) * CHN + kb + c8 * 4]);
            }
#pragma unroll
            for (int it = 0; it < 4; it++) {
                int idx = tid + it * 256;
                int k = idx >> 5, c32 = idx & 31;
                cp16(&sH[buf ^ 1][k][c32 * 4], &Hb[(size_t)(kb + k) * HWTOK + tb + c32 * 4]);
            }
            cp_commit();
        }
#pragma unroll
        for (int kk = 0; kk < 4; kk++) {
            uint32_t af[2][4], bf[4][2];
#pragma unroll
            for (int mt = 0; mt < 2; mt++) {
                int r0 = m0 + mt * 16 + q4;
                af[mt][0] = __float_as_uint(sW[buf][r0][kk * 8 + r4]);
                af[mt][1] = __float_as_uint(sW[buf][r0 + 8][kk * 8 + r4]);
                af[mt][2] = __float_as_uint(sW[buf][r0][kk * 8 + r4 + 4]);
                af[mt][3] = __float_as_uint(sW[buf][r0 + 8][kk * 8 + r4 + 4]);
            }
            if (MODE == 0) {
                int c0 = kt * 32 + kk * 8 + r4;
                float a0 = sA[c0], b0 = sB[c0];
                float a1 = sA[c0 + 4], b1 = sB[c0 + 4];
#pragma unroll
                for (int nn = 0; nn < 4; nn++) {
                    bf[nn][0] = __float_as_uint(fmaf(sH[buf][kk * 8 + r4][n0 + nn * 8 + q4], a0, b0));
                    bf[nn][1] = __float_as_uint(fmaf(sH[buf][kk * 8 + r4 + 4][n0 + nn * 8 + q4], a1, b1));
                }
            } else {
#pragma unroll
                for (int nn = 0; nn < 4; nn++) {
                    bf[nn][0] = __float_as_uint(sH[buf][kk * 8 + r4][n0 + nn * 8 + q4]);
                    bf[nn][1] = __float_as_uint(sH[buf][kk * 8 + r4 + 4][n0 + nn * 8 + q4]);
                }
            }
#pragma unroll
            for (int mt = 0; mt < 2; mt++)
#pragma unroll
                for (int nn = 0; nn < 4; nn++) mma_tf32(acc[mt][nn], af[mt], bf[nn]);
        }
    }
#pragma unroll
    for (int mt = 0; mt < 2; mt++) {
        int o = ob + m0 + mt * 16 + q4;
        float bi0 = bias[o], bi1 = bias[o + 8];
#pragma unroll
        for (int nn = 0; nn < 4; nn++) {
            int t = tb + n0 + nn * 8 + 2 * r4;
            float2 v0 = make_float2(acc[mt][nn][0] + bi0, acc[mt][nn][1] + bi0);
            float2 v1 = make_float2(acc[mt][nn][2] + bi1, acc[mt][nn][3] + bi1);
            if (MODE == 1) {
                float2 r0 = *(const float2*)&resid[((size_t)b * CHN + o) * HWTOK + t];
                float2 r1 = *(const float2*)&resid[((size_t)b * CHN + o + 8) * HWTOK + t];
                v0.x += r0.x; v0.y += r0.y;
                v1.x += r1.x; v1.y += r1.y;
            }
            *(float2*)&out[((size_t)b * OC + o) * HWTOK + t] = v0;
            *(float2*)&out[((size_t)b * OC + o + 8) * HWTOK + t] = v1;
        }
    }
}

// ---------------------------------------------------------------------------
// tf32 flash attention: 128-query tile, 4 warps x 32 rows, 32-key chunks,
// 2-stage cp.async pipeline, ONE barrier per chunk, log2-domain softmax.
// ZERO-shuffle PV: mma-k position k maps to key {2k, 2k-7}, which makes the
// S C-fragment exactly the PV A-fragment (af = {c0,c2,c1,c3}); V B-fragment
// reads adjacent-key float2.  Per-mt softmax+PV interleaved for ILP.
// ---------------------------------------------------------------------------
__global__ __launch_bounds__(128, 4) void attn_kernel() {
    __shared__ float dsm[5120];  // sK[2][32][40] | sV[2][32][40]; epi reuses as [32][132]
    float(*sK)[32][40] = (float(*)[32][40])dsm;
    float(*sV)[32][40] = (float(*)[32][40])(dsm + 2 * 32 * 40);

    int tid = threadIdx.x;
    int warp = tid >> 5, lane = tid & 31;
    int q4 = lane >> 2, r4 = lane & 3;
    int bh = blockIdx.x;
    int b = bh >> 3, n = bh & 7;
    int qb = blockIdx.y * 128;
    int rbase = warp * 32;

    const float SC = 0.25501333583834134f;  // (1/sqrt(32)) * log2(e)
    const float* Qp = g_qkv + ((size_t)b * 768 + n * HDIM) * HWTOK;
    const float* Kp = g_qkv + ((size_t)b * 768 + 256 + n * HDIM) * HWTOK;
    const float* Vp = g_qkv + ((size_t)b * 768 + 512 + n * HDIM) * HWTOK;

    // prologue: prefetch chunk 0 into buf 0
#pragma unroll
    for (int it = 0; it < 2; it++) {
        int idx = tid + it * 128;
        int d = idx >> 3, c8 = idx & 7;
        cp16(&sK[0][d][c8 * 4], Kp + (size_t)d * HWTOK + c8 * 4);
        cp16(&sV[0][d][c8 * 4], Vp + (size_t)d * HWTOK + c8 * 4);
    }
    cp_commit();

    // Q fragments persistent in registers (pre-scaled into log2 domain)
    uint32_t qf[2][4][4];
#pragma unroll
    for (int mt = 0; mt < 2; mt++) {
        int row = qb + rbase + mt * 16 + q4;
#pragma unroll
        for (int kk = 0; kk < 4; kk++) {
            int d0 = kk * 8 + r4;
            qf[mt][kk][0] = __float_as_uint(Qp[(size_t)d0 * HWTOK + row] * SC);
            qf[mt][kk][1] = __float_as_uint(Qp[(size_t)d0 * HWTOK + row + 8] * SC);
            qf[mt][kk][2] = __float_as_uint(Qp[(size_t)(d0 + 4) * HWTOK + row] * SC);
            qf[mt][kk][3] = __float_as_uint(Qp[(size_t)(d0 + 4) * HWTOK + row + 8] * SC);
        }
    }

    float mrow[2][2] = {{-3.0e38f, -3.0e38f}, {-3.0e38f, -3.0e38f}};
    float lrow[2][2] = {{0.f, 0.f}, {0.f, 0.f}};
    float O[2][4][4] = {};

    for (int ci = 0; ci < 128; ci++) {
        int st = ci & 1;
        cp_wait<0>();     // chunk ci landed
        __syncthreads();  // visible to all; prior reads of buf st done
        if (ci + 1 < 128) {
            int kc = (ci + 1) * 32;
#pragma unroll
            for (int it = 0; it < 2; it++) {
                int idx = tid + it * 128;
                int d = idx >> 3, c8 = idx & 7;
                cp16(&sK[st ^ 1][d][c8 * 4], Kp + (size_t)d * HWTOK + kc + c8 * 4);
                cp16(&sV[st ^ 1][d][c8 * 4], Vp + (size_t)d * HWTOK + kc + c8 * 4);
            }
            cp_commit();
        }

        // S = Q K^T  [2 mtiles][4 ntiles]
        float S[2][4][4] = {};
#pragma unroll
        for (int kk = 0; kk < 4; kk++) {
#pragma unroll
            for (int nn = 0; nn < 4; nn++) {
                uint32_t kf[2];
                kf[0] = __float_as_uint(sK[st][kk * 8 + r4][nn * 8 + q4]);
                kf[1] = __float_as_uint(sK[st][kk * 8 + r4 + 4][nn * 8 + q4]);
                mma_tf32(S[0][nn], qf[0][kk], kf);
                mma_tf32(S[1][nn], qf[1][kk], kf);
            }
        }

        // per-mt: softmax (log2 domain) then PV — interleaved so mt1 softmax
        // hides under mt0 PV tensor work
#pragma unroll
        for (int mt = 0; mt < 2; mt++) {
#pragma unroll
            for (int rh = 0; rh < 2; rh++) {
                float mx = -3.0e38f;
#pragma unroll
                for (int nn = 0; nn < 4; nn++) {
                    mx = fmaxf(mx, S[mt][nn][rh * 2]);
                    mx = fmaxf(mx, S[mt][nn][rh * 2 + 1]);
                }
                mx = fmaxf(mx, __shfl_xor_sync(0xffffffffu, mx, 1));
                mx = fmaxf(mx, __shfl_xor_sync(0xffffffffu, mx, 2));
                float mold = mrow[mt][rh];
                float mnew = fmaxf(mold, mx);
                float corr = ex2(mold - mnew);
                float ls = 0.f;
#pragma unroll
                for (int nn = 0; nn < 4; nn++) {
                    float p0 = ex2(S[mt][nn][rh * 2] - mnew);
                    float p1 = ex2(S[mt][nn][rh * 2 + 1] - mnew);
                    S[mt][nn][rh * 2] = p0;
                    S[mt][nn][rh * 2 + 1] = p1;
                    ls += p0 + p1;
                }
                ls += __shfl_xor_sync(0xffffffffu, ls, 1);
                ls += __shfl_xor_sync(0xffffffffu, ls, 2);
                lrow[mt][rh] = lrow[mt][rh] * corr + ls;
                mrow[mt][rh] = mnew;
#pragma unroll
                for (int nd = 0; nd < 4; nd++) {
                    O[mt][nd][rh * 2] *= corr;
                    O[mt][nd][rh * 2 + 1] *= corr;
                }
            }

            // O[mt] += P V  (A-frag = C-frag renamed; B-frag = adjacent-key pair)
#pragma unroll
            for (int kk = 0; kk < 4; kk++) {
                uint32_t af[4];
                af[0] = __float_as_uint(S[mt][kk][0]);
                af[1] = __float_as_uint(S[mt][kk][2]);
                af[2] = __float_as_uint(S[mt][kk][1]);
                af[3] = __float_as_uint(S[mt][kk][3]);
#pragma unroll
                for (int nd = 0; nd < 4; nd++) {
                    float2 vv = *(const float2*)&sV[st][nd * 8 + q4][kk * 8 + 2 * r4];
                    uint32_t vf[2] = {__float_as_uint(vv.x), __float_as_uint(vv.y)};
                    mma_tf32(O[mt][nd], af, vf);
                }
            }
        }
    }

    // epilogue: normalize, stage [d][row] via smem, coalesced store
    __syncthreads();
    float* sOut = dsm;  // [32][132]
#pragma unroll
    for (int mt = 0; mt < 2; mt++) {
#pragma unroll
        for (int rh = 0; rh < 2; rh++) {
            float inv = 1.f / lrow[mt][rh];
            int row = rbase + mt * 16 + q4 + rh * 8;
#pragma unroll
            for (int nd = 0; nd < 4; nd++) {
                sOut[(nd * 8 + 2 * r4) * 132 + row] = O[mt][nd][rh * 2] * inv;
                sOut[(nd * 8 + 2 * r4 + 1) * 132 + row] = O[mt][nd][rh * 2 + 1] * inv;
            }
        }
    }
    __syncthreads();
    float* aop = g_ao + ((size_t)b * CHN + n * HDIM) * HWTOK;
#pragma unroll
    for (int it = 0; it < 32; it++) {
        int idx = tid + it * 128;
        int d = idx >> 7, r = idx & 127;
        aop[(size_t)d * HWTOK + qb + r] = sOut[d * 132 + r];
    }
}

// ---------------------------------------------------------------------------
extern "C" void kernel_launch(void* const* d_in, const int* in_sizes, int n_in,
                              void* d_out, int out_size) {
    const float* x = (const float*)d_in[0];
    const float* w_qkv = (const float*)d_in[1];
    const float* b_qkv = (const float*)d_in[2];
    const float* w_proj = (const float*)d_in[3];
    const float* b_proj = (const float*)d_in[4];
    const float* gamma = (const float*)d_in[5];
    const float* beta = (const float*)d_in[6];
    float* out = (float*)d_out;

    const int MM_SMEM = (2 * 64 * 36 + 2 * 32 * 136) * 4;  // 53248
    static bool attr_set = false;
    if (!attr_set) {
        cudaFuncSetAttribute(mm_tc<0>, cudaFuncAttributeMaxDynamicSharedMemorySize, MM_SMEM);
        cudaFuncSetAttribute(mm_tc<1>, cudaFuncAttributeMaxDynamicSharedMemorySize, MM_SMEM);
        attr_set = true;
    }

    gn_stats<<<BATCH * NGROUP, 256>>>(x);
    mm_tc<0><<<dim3(HWTOK / 128, (3 * CHN) / 64, BATCH), 256, MM_SMEM>>>(
        w_qkv, b_qkv, x, nullptr, gamma, beta, nullptr);
    attn_kernel<<<dim3(BATCH * NHEAD, HWTOK / 128), 128>>>();
    mm_tc<1><<<dim3(HWTOK / 128, CHN / 64, BATCH), 256, MM_SMEM>>>(
        w_proj, b_proj, nullptr, x, nullptr, nullptr, out);
}